// round 10
// baseline (speedup 1.0000x reference)
#include <cuda_runtime.h>
#include <cuda_bf16.h>
#include <cstdint>

#define EMB 128
#define MAX_ATOMS 20000
#define AP 136                      // padded row stride (bf16 elems) = 272 B
#define MROWS 160                   // rows per MLP CTA (10 m16 tiles)

// ---------------------------------------------------------------------------
__device__ __align__(16) float g_node[MAX_ATOMS * EMB];           // segment-sum acc
__device__ __align__(16) __nv_bfloat16 g_wb[4 * 2 * 128 * AP];    // [layer][hi/lo][n*AP+k]
__device__ int g_is64;

// ---------------------------------------------------------------------------
__device__ __forceinline__ uint32_t smem_to_u32(const void* p) {
    uint32_t a;
    asm("{ .reg .u64 t; cvta.to.shared.u64 t, %1; cvt.u32.u64 %0, t; }" : "=r"(a) : "l"(p));
    return a;
}

__device__ __forceinline__ void ldsm_x4(uint32_t addr, uint32_t r[4]) {
    asm volatile("ldmatrix.sync.aligned.m8n8.x4.shared.b16 {%0,%1,%2,%3}, [%4];"
                 : "=r"(r[0]), "=r"(r[1]), "=r"(r[2]), "=r"(r[3]) : "r"(addr));
}

__device__ __forceinline__ void mma16816(float d[4], const uint32_t a[4],
                                         uint32_t b0, uint32_t b1) {
    asm volatile(
        "mma.sync.aligned.m16n8k16.row.col.f32.bf16.bf16.f32 "
        "{%0,%1,%2,%3}, {%4,%5,%6,%7}, {%8,%9}, {%0,%1,%2,%3};"
        : "+f"(d[0]), "+f"(d[1]), "+f"(d[2]), "+f"(d[3])
        : "r"(a[0]), "r"(a[1]), "r"(a[2]), "r"(a[3]), "r"(b0), "r"(b1));
}

__device__ __forceinline__ uint32_t pack_bf16x2(float x, float y) {
    __nv_bfloat162 v;
    v.x = __float2bfloat16_rn(x);
    v.y = __float2bfloat16_rn(y);
    return *reinterpret_cast<uint32_t*>(&v);
}

__device__ __forceinline__ void cp_async16(uint32_t smem_addr, const void* gptr) {
    asm volatile("cp.async.cg.shared.global [%0], [%1], 16;"
                 :: "r"(smem_addr), "l"(gptr));
}
__device__ __forceinline__ void cp_async_commit() {
    asm volatile("cp.async.commit_group;" ::: "memory");
}
__device__ __forceinline__ void cp_async_wait0() {
    asm volatile("cp.async.wait_group 0;" ::: "memory");
}

// fast swish: x * sigmoid(x) via EX2 + RCP (no IEEE div)
__device__ __forceinline__ float fast_swish(float x) {
    float e = __expf(-x);
    return __fdividef(x, 1.0f + e);
}

// ---------------------------------------------------------------------------
// Fused setup, grid-stride (257 blocks):
//   blocks 0..255 : weight prep (1 elem/thread) + grid-stride zero of g_node
//   block 256     : dtype detect + tail of zero loop
// ---------------------------------------------------------------------------
__global__ void setup_kernel(const float* __restrict__ W1, const float* __restrict__ W2,
                             const float* __restrict__ W3, const float* __restrict__ W4,
                             const int* __restrict__ nbr, int n_words, int n4)
{
    int b = blockIdx.x;
    int tid = threadIdx.x;

    // grid-stride zero of g_node (all 257 blocks participate)
    float4* gz = reinterpret_cast<float4*>(g_node);
    for (int i = b * 256 + tid; i < n4; i += 257 * 256)
        gz[i] = make_float4(0.f, 0.f, 0.f, 0.f);

    if (b < 256) {
        int idx = b * 256 + tid;           // 65536 elements
        int l = idx >> 14;
        int e = idx & 16383;
        int k = e >> 7, n = e & 127;       // W row-major: W[k][n]
        const float* W = (l == 0) ? W1 : (l == 1) ? W2 : (l == 2) ? W3 : W4;
        float x = W[e];
        __nv_bfloat16 hi = __float2bfloat16_rn(x);
        __nv_bfloat16 lo = __float2bfloat16_rn(x - __bfloat162float(hi));
        g_wb[(l * 2 + 0) * (128 * AP) + n * AP + k] = hi;
        g_wb[(l * 2 + 1) * (128 * AP) + n * AP + k] = lo;
        return;
    }
    // dtype detection (block 256)
    __shared__ int any;
    if (tid == 0) any = 0;
    __syncthreads();
    int found = 0;
    for (int i = tid; i < 2048; i += blockDim.x) {
        int idx = 2 * i + 1;
        if (idx < n_words && nbr[idx] != 0) found = 1;
    }
    if (found) atomicOr(&any, 1);
    __syncthreads();
    if (tid == 0) g_is64 = (any == 0) ? 1 : 0;
}

// ---------------------------------------------------------------------------
// Edge pass: one warp = 4 edges. PDL: W_edge smem fill + rbf load run BEFORE
// cudaGridDependencySynchronize(); g_is64 / nbr / atomics after.
// ---------------------------------------------------------------------------
__global__ void __launch_bounds__(256, 5) edge_kernel(
    const float* __restrict__ m_ji,
    const float* __restrict__ e_rbf,
    const int*   __restrict__ nbr,
    const float* __restrict__ W_edge,
    int E)
{
    __shared__ float sWe[6 * 128];
    int tid = threadIdx.x;
    for (int i = tid; i < 6 * 128; i += blockDim.x) sWe[i] = W_edge[i];
    __syncthreads();

    int warp = (int)((blockIdx.x * (long long)blockDim.x + tid) >> 5);
    int lane = tid & 31;
    long long e0 = (long long)warp * 4;
    if (e0 >= E) return;

    // upstream-independent loads (overlap with setup's tail)
    float rbf = 0.0f;
    if (lane < 24 && e0 * 6 + lane < (long long)E * 6)
        rbf = __ldcs(&e_rbf[e0 * 6 + lane]);

    const float4* we4 = reinterpret_cast<const float4*>(sWe);
    float4 wv[6];
#pragma unroll
    for (int r = 0; r < 6; r++) wv[r] = we4[r * 32 + lane];

    // wait for setup: g_node zeroed + g_is64 valid
    cudaGridDependencySynchronize();

    int is64 = g_is64;
    int d = 0;
    if (lane < 4 && e0 + lane < E)
        d = is64 ? __ldcs(&nbr[(e0 + lane) * 4 + 2]) : __ldcs(&nbr[(e0 + lane) * 2 + 1]);

#pragma unroll
    for (int j = 0; j < 4; j++) {
        if (e0 + j >= E) break;
        float4 m = __ldcs(&reinterpret_cast<const float4*>(m_ji + (e0 + j) * EMB)[lane]);
        float4 w = make_float4(0.f, 0.f, 0.f, 0.f);
#pragma unroll
        for (int r = 0; r < 6; r++) {
            float c = __shfl_sync(0xffffffffu, rbf, j * 6 + r);
            w.x = fmaf(c, wv[r].x, w.x);
            w.y = fmaf(c, wv[r].y, w.y);
            w.z = fmaf(c, wv[r].z, w.z);
            w.w = fmaf(c, wv[r].w, w.w);
        }
        float4 o = make_float4(w.x * m.x, w.y * m.y, w.z * m.z, w.w * m.w);
        int dj = __shfl_sync(0xffffffffu, d, j);
        atomicAdd(reinterpret_cast<float4*>(&g_node[(long long)dj * EMB + lane * 4]), o);
    }
}

// ---------------------------------------------------------------------------
// MLP via mma.sync bf16 split (256 thr, 8 warps, 160 rows/CTA, 125 CTAs).
// PDL: weight cp.async + bias loads pre-sync; g_node read post-sync.
// smem: Ahi(43520) Alo(43520) Bhi(34816) Blo(34816) bias(1536)
// ---------------------------------------------------------------------------
#define SA_HI 0
#define SA_LO 43520
#define SB_HI 87040
#define SB_LO 121856
#define SBIAS 156672
#define SMEM_TOTAL (156672 + 1536)
#define B_CHUNKS 2176               // (128*AP*2 bytes)/16 = float4 count per buffer

__device__ __forceinline__ void issue_b_copy(uint32_t sb, int layer, int tid) {
    const char* srcH = reinterpret_cast<const char*>(g_wb + (layer * 2 + 0) * (128 * AP));
    const char* srcL = reinterpret_cast<const char*>(g_wb + (layer * 2 + 1) * (128 * AP));
#pragma unroll 4
    for (int i = tid; i < B_CHUNKS; i += 256) {
        cp_async16(sb + SB_HI + i * 16, srcH + i * 16);
        cp_async16(sb + SB_LO + i * 16, srcL + i * 16);
    }
    cp_async_commit();
}

template <int MT>
__device__ __forceinline__ void layer_compute(
    uint32_t aH, uint32_t aL, uint32_t bH, uint32_t bL,
    const int* tiles, float acc[][8][4])
{
#pragma unroll
    for (int mt = 0; mt < MT; mt++)
#pragma unroll
        for (int nt = 0; nt < 8; nt++)
#pragma unroll
            for (int q = 0; q < 4; q++) acc[mt][nt][q] = 0.0f;

#pragma unroll
    for (int k0 = 0; k0 < 128; k0 += 16) {
        uint32_t ah[MT][4], al[MT][4];
#pragma unroll
        for (int mt = 0; mt < MT; mt++) {
            uint32_t toff = (uint32_t)(tiles[mt] * 16 * (AP * 2)) + k0 * 2;
            ldsm_x4(aH + toff, ah[mt]);
            ldsm_x4(aL + toff, al[mt]);
        }
#pragma unroll
        for (int nt2 = 0; nt2 < 4; nt2++) {
            uint32_t bh[4], bl[4];
            ldsm_x4(bH + nt2 * 16 * (AP * 2) + k0 * 2, bh);
            ldsm_x4(bL + nt2 * 16 * (AP * 2) + k0 * 2, bl);
#pragma unroll
            for (int nt = 0; nt < 2; nt++) {
                int nti = nt2 * 2 + nt;
#pragma unroll
                for (int mt = 0; mt < MT; mt++) {
                    mma16816(acc[mt][nti], ah[mt], bh[nt * 2], bh[nt * 2 + 1]);
                    mma16816(acc[mt][nti], ah[mt], bl[nt * 2], bl[nt * 2 + 1]);
                    mma16816(acc[mt][nti], al[mt], bh[nt * 2], bh[nt * 2 + 1]);
                }
            }
        }
    }
}

template <int MT>
__device__ __forceinline__ void layer_epilogue_act(
    char* smem, const float* bia, const int* tiles, float acc[][8][4],
    int wcol, int g, int t2)
{
#pragma unroll
    for (int mt = 0; mt < MT; mt++) {
        int rA = tiles[mt] * 16 + g;
        int rB = rA + 8;
#pragma unroll
        for (int nt = 0; nt < 8; nt++) {
            int col = wcol * 64 + nt * 8 + t2;
            float b0 = bia[col], b1v = bia[col + 1];
            float s0 = fast_swish(acc[mt][nt][0] + b0);
            float s1 = fast_swish(acc[mt][nt][1] + b1v);
            float s2 = fast_swish(acc[mt][nt][2] + b0);
            float s3 = fast_swish(acc[mt][nt][3] + b1v);
            __nv_bfloat16 h0 = __float2bfloat16_rn(s0);
            __nv_bfloat16 h1 = __float2bfloat16_rn(s1);
            __nv_bfloat16 h2 = __float2bfloat16_rn(s2);
            __nv_bfloat16 h3 = __float2bfloat16_rn(s3);
            __nv_bfloat162 hv;
            hv.x = h0; hv.y = h1;
            *reinterpret_cast<uint32_t*>(smem + SA_HI + rA * (AP * 2) + col * 2) =
                *reinterpret_cast<uint32_t*>(&hv);
            hv.x = h2; hv.y = h3;
            *reinterpret_cast<uint32_t*>(smem + SA_HI + rB * (AP * 2) + col * 2) =
                *reinterpret_cast<uint32_t*>(&hv);
            *reinterpret_cast<uint32_t*>(smem + SA_LO + rA * (AP * 2) + col * 2) =
                pack_bf16x2(s0 - __bfloat162float(h0), s1 - __bfloat162float(h1));
            *reinterpret_cast<uint32_t*>(smem + SA_LO + rB * (AP * 2) + col * 2) =
                pack_bf16x2(s2 - __bfloat162float(h2), s3 - __bfloat162float(h3));
        }
    }
}

template <int MT>
__device__ __forceinline__ void layer_epilogue_out(
    float* __restrict__ out, const int* tiles, float acc[][8][4],
    int row0, int natoms, int wcol, int g, int t2)
{
#pragma unroll
    for (int mt = 0; mt < MT; mt++) {
        int rA = row0 + tiles[mt] * 16 + g;
        int rB = rA + 8;
#pragma unroll
        for (int nt = 0; nt < 8; nt++) {
            int col = wcol * 64 + nt * 8 + t2;
            if (rA < natoms)
                *reinterpret_cast<float2*>(&out[(long long)rA * EMB + col]) =
                    make_float2(acc[mt][nt][0], acc[mt][nt][1]);
            if (rB < natoms)
                *reinterpret_cast<float2*>(&out[(long long)rB * EMB + col]) =
                    make_float2(acc[mt][nt][2], acc[mt][nt][3]);
        }
    }
}

__global__ void __launch_bounds__(256, 1) mlp_kernel(
    const float* __restrict__ b1, const float* __restrict__ b2,
    const float* __restrict__ b3,
    float* __restrict__ out, int natoms)
{
    extern __shared__ char smem[];
    uint32_t sb = smem_to_u32(smem);
    int tid = threadIdx.x;
    int wid = tid >> 5;
    int lane = tid & 31;
    int wrow = wid >> 1;              // 0..3
    int wcol = wid & 1;               // 0..1
    int row0 = blockIdx.x * MROWS;

    int tiles[3];
    tiles[0] = wrow;
    tiles[1] = wrow + 4;
    tiles[2] = wrow + 8;              // valid only for wrow<2
    bool has3 = (wrow < 2);

    // pre-sync prologue: weight copy (g_wb from setup, long complete) + biases
    issue_b_copy(sb, 0, tid);

    if (tid < 128) {
        float* bia = reinterpret_cast<float*>(smem + SBIAS);
        bia[tid] = b1[tid];
        bia[128 + tid] = b2[tid];
        bia[256 + tid] = b3[tid];
    }

    // wait for edge kernel's atomics into g_node
    cudaGridDependencySynchronize();

    // First-layer A: fp32 g_node -> bf16 hi/lo, padded [row][k] layout.
    for (int i = tid; i < MROWS * 32; i += 256) {
        int r = i >> 5, c4 = i & 31;
        int gr = row0 + r;
        float4 v = make_float4(0.f, 0.f, 0.f, 0.f);
        if (gr < natoms)
            v = __ldcs(&reinterpret_cast<const float4*>(&g_node[(long long)gr * EMB])[c4]);
        __nv_bfloat16 hx = __float2bfloat16_rn(v.x), hy = __float2bfloat16_rn(v.y);
        __nv_bfloat16 hz = __float2bfloat16_rn(v.z), hw = __float2bfloat16_rn(v.w);
        uint2 hp, lp;
        __nv_bfloat162 t;
        t.x = hx; t.y = hy; hp.x = *reinterpret_cast<uint32_t*>(&t);
        t.x = hz; t.y = hw; hp.y = *reinterpret_cast<uint32_t*>(&t);
        lp.x = pack_bf16x2(v.x - __bfloat162float(hx), v.y - __bfloat162float(hy));
        lp.y = pack_bf16x2(v.z - __bfloat162float(hz), v.w - __bfloat162float(hw));
        *reinterpret_cast<uint2*>(smem + SA_HI + r * (AP * 2) + c4 * 8) = hp;
        *reinterpret_cast<uint2*>(smem + SA_LO + r * (AP * 2) + c4 * 8) = lp;
    }

    uint32_t a_lane = (uint32_t)((lane & 15) * (AP * 2) + ((lane >> 4) * 8) * 2);
    uint32_t aH = sb + SA_HI + a_lane;
    uint32_t aL = sb + SA_LO + a_lane;
    uint32_t b_row = (uint32_t)(((lane >> 4) & 1) * 8 + (lane & 7));
    uint32_t b_k   = (uint32_t)(((lane >> 3) & 1) * 8);
    uint32_t b_off = (uint32_t)((wcol * 64 + b_row) * (AP * 2) + b_k * 2);
    uint32_t bH = sb + SB_HI + b_off;
    uint32_t bL = sb + SB_LO + b_off;

    const float* bias_all = reinterpret_cast<const float*>(smem + SBIAS);
    int g = lane >> 2;
    int t2 = (lane & 3) * 2;

    float acc[3][8][4];

    cp_async_wait0();
    __syncthreads();   // A + B(0) visible to all warps

    for (int layer = 0; layer < 4; layer++) {
        if (has3) layer_compute<3>(aH, aL, bH, bL, tiles, acc);
        else      layer_compute<2>(aH, aL, bH, bL, tiles, acc);

        __syncthreads();   // all A and B reads done -> safe to overwrite both

        if (layer < 3) {
            issue_b_copy(sb, layer + 1, tid);
            const float* bia = bias_all + layer * 128;
            if (has3) layer_epilogue_act<3>(smem, bia, tiles, acc, wcol, g, t2);
            else      layer_epilogue_act<2>(smem, bia, tiles, acc, wcol, g, t2);
            cp_async_wait0();
            __syncthreads();   // A(next) + B(next) visible
        } else {
            if (has3) layer_epilogue_out<3>(out, tiles, acc, row0, natoms, wcol, g, t2);
            else      layer_epilogue_out<2>(out, tiles, acc, row0, natoms, wcol, g, t2);
        }
    }
}

// ---------------------------------------------------------------------------
extern "C" void kernel_launch(void* const* d_in, const int* in_sizes, int n_in,
                              void* d_out, int out_size)
{
    const float* m_ji  = (const float*)d_in[0];
    const float* e_rbf = (const float*)d_in[1];
    const int*   nbr   = (const int*)d_in[2];

    int base = (n_in >= 12 && in_sizes[3] < 16) ? 4 : 3;
    const float* W_edge = (const float*)d_in[base + 0];
    const float* W1 = (const float*)d_in[base + 1];
    const float* b1 = (const float*)d_in[base + 2];
    const float* W2 = (const float*)d_in[base + 3];
    const float* b2 = (const float*)d_in[base + 4];
    const float* W3 = (const float*)d_in[base + 5];
    const float* b3 = (const float*)d_in[base + 6];
    const float* W4 = (const float*)d_in[base + 7];

    int E = in_sizes[1] / 6;
    int natoms = out_size / EMB;
    if (natoms > MAX_ATOMS) natoms = MAX_ATOMS;
    float* out = (float*)d_out;

    // setup: zero + weight prep + dtype detect (plain launch)
    int n4 = natoms * EMB / 4;
    setup_kernel<<<257, 256>>>(W1, W2, W3, W4, nbr, 2 * E, n4);

    // PDL attribute: allow dependent kernels to launch while upstream drains
    cudaLaunchAttribute pdl[1];
    pdl[0].id = cudaLaunchAttributeProgrammaticStreamSerialization;
    pdl[0].val.programmaticStreamSerializationAllowed = 1;

    // edge pass (PDL-dependent on setup)
    {
        int warps = (E + 3) / 4;
        int eblocks = (warps + 7) / 8;
        cudaLaunchConfig_t cfg = {};
        cfg.gridDim = dim3((unsigned)eblocks, 1, 1);
        cfg.blockDim = dim3(256, 1, 1);
        cfg.dynamicSmemBytes = 0;
        cfg.stream = 0;
        cfg.attrs = pdl;
        cfg.numAttrs = 1;
        cudaLaunchKernelEx(&cfg, edge_kernel, m_ji, e_rbf, nbr, W_edge, E);
    }

    // MLP (PDL-dependent on edge): single wave of 125 CTAs
    cudaFuncSetAttribute(mlp_kernel, cudaFuncAttributeMaxDynamicSharedMemorySize, SMEM_TOTAL);
    {
        int mlp_blocks = (natoms + MROWS - 1) / MROWS;
        cudaLaunchConfig_t cfg = {};
        cfg.gridDim = dim3((unsigned)mlp_blocks, 1, 1);
        cfg.blockDim = dim3(256, 1, 1);
        cfg.dynamicSmemBytes = SMEM_TOTAL;
        cfg.stream = 0;
        cfg.attrs = pdl;
        cfg.numAttrs = 1;
        cudaLaunchKernelEx(&cfg, mlp_kernel, b1, b2, b3, out, natoms);
    }
}

// round 11
// speedup vs baseline: 1.0414x; 1.0414x over previous
#include <cuda_runtime.h>
#include <cuda_bf16.h>
#include <cuda_fp16.h>
#include <cstdint>

#define EMB 128
#define MAX_ATOMS 20000
#define AP 136                      // padded row stride (fp16 elems) = 272 B
#define MROWS 160                   // rows per MLP CTA (10 m16 tiles)

// ---------------------------------------------------------------------------
__device__ __align__(16) float g_node[MAX_ATOMS * EMB];     // segment-sum acc
__device__ __align__(16) __half g_wh[4 * 128 * AP];         // [layer][n*AP+k] fp16 weights
__device__ int g_is64;

// ---------------------------------------------------------------------------
__device__ __forceinline__ uint32_t smem_to_u32(const void* p) {
    uint32_t a;
    asm("{ .reg .u64 t; cvta.to.shared.u64 t, %1; cvt.u32.u64 %0, t; }" : "=r"(a) : "l"(p));
    return a;
}

__device__ __forceinline__ void ldsm_x4(uint32_t addr, uint32_t r[4]) {
    asm volatile("ldmatrix.sync.aligned.m8n8.x4.shared.b16 {%0,%1,%2,%3}, [%4];"
                 : "=r"(r[0]), "=r"(r[1]), "=r"(r[2]), "=r"(r[3]) : "r"(addr));
}

__device__ __forceinline__ void mma16816h(float d[4], const uint32_t a[4],
                                          uint32_t b0, uint32_t b1) {
    asm volatile(
        "mma.sync.aligned.m16n8k16.row.col.f32.f16.f16.f32 "
        "{%0,%1,%2,%3}, {%4,%5,%6,%7}, {%8,%9}, {%0,%1,%2,%3};"
        : "+f"(d[0]), "+f"(d[1]), "+f"(d[2]), "+f"(d[3])
        : "r"(a[0]), "r"(a[1]), "r"(a[2]), "r"(a[3]), "r"(b0), "r"(b1));
}

__device__ __forceinline__ uint32_t pack_h2(float x, float y) {
    __half2 v;
    v.x = __float2half_rn(x);
    v.y = __float2half_rn(y);
    return *reinterpret_cast<uint32_t*>(&v);
}

__device__ __forceinline__ void cp_async16(uint32_t smem_addr, const void* gptr) {
    asm volatile("cp.async.cg.shared.global [%0], [%1], 16;"
                 :: "r"(smem_addr), "l"(gptr));
}
__device__ __forceinline__ void cp_async_commit() {
    asm volatile("cp.async.commit_group;" ::: "memory");
}
__device__ __forceinline__ void cp_async_wait0() {
    asm volatile("cp.async.wait_group 0;" ::: "memory");
}

// fast swish: x * sigmoid(x) via EX2 + RCP (no IEEE div)
__device__ __forceinline__ float fast_swish(float x) {
    float e = __expf(-x);
    return __fdividef(x, 1.0f + e);
}

// ---------------------------------------------------------------------------
// Fused setup, grid-stride (257 blocks):
//   blocks 0..255 : weight prep (fp16, 1 elem/thread) + grid-stride zero
//   block 256     : dtype detect + tail of zero loop
// ---------------------------------------------------------------------------
__global__ void setup_kernel(const float* __restrict__ W1, const float* __restrict__ W2,
                             const float* __restrict__ W3, const float* __restrict__ W4,
                             const int* __restrict__ nbr, int n_words, int n4)
{
    int b = blockIdx.x;
    int tid = threadIdx.x;

    float4* gz = reinterpret_cast<float4*>(g_node);
    for (int i = b * 256 + tid; i < n4; i += 257 * 256)
        gz[i] = make_float4(0.f, 0.f, 0.f, 0.f);

    if (b < 256) {
        int idx = b * 256 + tid;           // 65536 elements
        int l = idx >> 14;
        int e = idx & 16383;
        int k = e >> 7, n = e & 127;       // W row-major: W[k][n]
        const float* W = (l == 0) ? W1 : (l == 1) ? W2 : (l == 2) ? W3 : W4;
        g_wh[l * (128 * AP) + n * AP + k] = __float2half_rn(W[e]);
        return;
    }
    __shared__ int any;
    if (tid == 0) any = 0;
    __syncthreads();
    int found = 0;
    for (int i = tid; i < 2048; i += blockDim.x) {
        int idx = 2 * i + 1;
        if (idx < n_words && nbr[idx] != 0) found = 1;
    }
    if (found) atomicOr(&any, 1);
    __syncthreads();
    if (tid == 0) g_is64 = (any == 0) ? 1 : 0;
}

// ---------------------------------------------------------------------------
// Edge pass (unchanged): one warp = 4 edges, PDL prologue split.
// ---------------------------------------------------------------------------
__global__ void __launch_bounds__(256, 5) edge_kernel(
    const float* __restrict__ m_ji,
    const float* __restrict__ e_rbf,
    const int*   __restrict__ nbr,
    const float* __restrict__ W_edge,
    int E)
{
    __shared__ float sWe[6 * 128];
    int tid = threadIdx.x;
    for (int i = tid; i < 6 * 128; i += blockDim.x) sWe[i] = W_edge[i];
    __syncthreads();

    int warp = (int)((blockIdx.x * (long long)blockDim.x + tid) >> 5);
    int lane = tid & 31;
    long long e0 = (long long)warp * 4;
    if (e0 >= E) return;

    float rbf = 0.0f;
    if (lane < 24 && e0 * 6 + lane < (long long)E * 6)
        rbf = __ldcs(&e_rbf[e0 * 6 + lane]);

    const float4* we4 = reinterpret_cast<const float4*>(sWe);
    float4 wv[6];
#pragma unroll
    for (int r = 0; r < 6; r++) wv[r] = we4[r * 32 + lane];

    cudaGridDependencySynchronize();

    int is64 = g_is64;
    int d = 0;
    if (lane < 4 && e0 + lane < E)
        d = is64 ? __ldcs(&nbr[(e0 + lane) * 4 + 2]) : __ldcs(&nbr[(e0 + lane) * 2 + 1]);

#pragma unroll
    for (int j = 0; j < 4; j++) {
        if (e0 + j >= E) break;
        float4 m = __ldcs(&reinterpret_cast<const float4*>(m_ji + (e0 + j) * EMB)[lane]);
        float4 w = make_float4(0.f, 0.f, 0.f, 0.f);
#pragma unroll
        for (int r = 0; r < 6; r++) {
            float c = __shfl_sync(0xffffffffu, rbf, j * 6 + r);
            w.x = fmaf(c, wv[r].x, w.x);
            w.y = fmaf(c, wv[r].y, w.y);
            w.z = fmaf(c, wv[r].z, w.z);
            w.w = fmaf(c, wv[r].w, w.w);
        }
        float4 o = make_float4(w.x * m.x, w.y * m.y, w.z * m.z, w.w * m.w);
        int dj = __shfl_sync(0xffffffffu, d, j);
        atomicAdd(reinterpret_cast<float4*>(&g_node[(long long)dj * EMB + lane * 4]), o);
    }
}

// ---------------------------------------------------------------------------
// MLP via fp16 mma.sync, asymmetric split: A = Ah + Al (both fp16, exact to
// 22 bits), B = fp16(W) single. 2 MMAs per tile-kstep instead of 3.
// 256 thr, 8 warps, 160 rows/CTA, 125 CTAs single wave.
// smem: Ahi(43520) Alo(43520) B(34816) bias(1536)
// ---------------------------------------------------------------------------
#define SA_HI 0
#define SA_LO 43520
#define SB    87040
#define SBIAS 121856
#define SMEM_TOTAL (121856 + 1536)
#define B_CHUNKS 2176               // 34816 B / 16 = float4 count for one buffer

__device__ __forceinline__ void issue_b_copy(uint32_t sb, int layer, int tid) {
    const char* src = reinterpret_cast<const char*>(g_wh + layer * (128 * AP));
#pragma unroll 4
    for (int i = tid; i < B_CHUNKS; i += 256)
        cp_async16(sb + SB + i * 16, src + i * 16);
    cp_async_commit();
}

template <int MT>
__device__ __forceinline__ void layer_compute(
    uint32_t aH, uint32_t aL, uint32_t bB,
    const int* tiles, float acc[][8][4])
{
#pragma unroll
    for (int mt = 0; mt < MT; mt++)
#pragma unroll
        for (int nt = 0; nt < 8; nt++)
#pragma unroll
            for (int q = 0; q < 4; q++) acc[mt][nt][q] = 0.0f;

#pragma unroll
    for (int k0 = 0; k0 < 128; k0 += 16) {
        uint32_t ah[MT][4], al[MT][4];
#pragma unroll
        for (int mt = 0; mt < MT; mt++) {
            uint32_t toff = (uint32_t)(tiles[mt] * 16 * (AP * 2)) + k0 * 2;
            ldsm_x4(aH + toff, ah[mt]);
            ldsm_x4(aL + toff, al[mt]);
        }
#pragma unroll
        for (int nt2 = 0; nt2 < 4; nt2++) {
            uint32_t bh[4];
            ldsm_x4(bB + nt2 * 16 * (AP * 2) + k0 * 2, bh);
#pragma unroll
            for (int nt = 0; nt < 2; nt++) {
                int nti = nt2 * 2 + nt;
#pragma unroll
                for (int mt = 0; mt < MT; mt++) {
                    mma16816h(acc[mt][nti], ah[mt], bh[nt * 2], bh[nt * 2 + 1]);
                    mma16816h(acc[mt][nti], al[mt], bh[nt * 2], bh[nt * 2 + 1]);
                }
            }
        }
    }
}

template <int MT>
__device__ __forceinline__ void layer_epilogue_act(
    char* smem, const float* bia, const int* tiles, float acc[][8][4],
    int wcol, int g, int t2)
{
#pragma unroll
    for (int mt = 0; mt < MT; mt++) {
        int rA = tiles[mt] * 16 + g;
        int rB = rA + 8;
#pragma unroll
        for (int nt = 0; nt < 8; nt++) {
            int col = wcol * 64 + nt * 8 + t2;
            float b0 = bia[col], b1v = bia[col + 1];
            float s0 = fast_swish(acc[mt][nt][0] + b0);
            float s1 = fast_swish(acc[mt][nt][1] + b1v);
            float s2 = fast_swish(acc[mt][nt][2] + b0);
            float s3 = fast_swish(acc[mt][nt][3] + b1v);
            __half h0 = __float2half_rn(s0);
            __half h1 = __float2half_rn(s1);
            __half h2 = __float2half_rn(s2);
            __half h3 = __float2half_rn(s3);
            __half2 hv;
            hv.x = h0; hv.y = h1;
            *reinterpret_cast<uint32_t*>(smem + SA_HI + rA * (AP * 2) + col * 2) =
                *reinterpret_cast<uint32_t*>(&hv);
            hv.x = h2; hv.y = h3;
            *reinterpret_cast<uint32_t*>(smem + SA_HI + rB * (AP * 2) + col * 2) =
                *reinterpret_cast<uint32_t*>(&hv);
            *reinterpret_cast<uint32_t*>(smem + SA_LO + rA * (AP * 2) + col * 2) =
                pack_h2(s0 - __half2float(h0), s1 - __half2float(h1));
            *reinterpret_cast<uint32_t*>(smem + SA_LO + rB * (AP * 2) + col * 2) =
                pack_h2(s2 - __half2float(h2), s3 - __half2float(h3));
        }
    }
}

template <int MT>
__device__ __forceinline__ void layer_epilogue_out(
    float* __restrict__ out, const int* tiles, float acc[][8][4],
    int row0, int natoms, int wcol, int g, int t2)
{
#pragma unroll
    for (int mt = 0; mt < MT; mt++) {
        int rA = row0 + tiles[mt] * 16 + g;
        int rB = rA + 8;
#pragma unroll
        for (int nt = 0; nt < 8; nt++) {
            int col = wcol * 64 + nt * 8 + t2;
            if (rA < natoms)
                *reinterpret_cast<float2*>(&out[(long long)rA * EMB + col]) =
                    make_float2(acc[mt][nt][0], acc[mt][nt][1]);
            if (rB < natoms)
                *reinterpret_cast<float2*>(&out[(long long)rB * EMB + col]) =
                    make_float2(acc[mt][nt][2], acc[mt][nt][3]);
        }
    }
}

__global__ void __launch_bounds__(256, 1) mlp_kernel(
    const float* __restrict__ b1, const float* __restrict__ b2,
    const float* __restrict__ b3,
    float* __restrict__ out, int natoms)
{
    extern __shared__ char smem[];
    uint32_t sb = smem_to_u32(smem);
    int tid = threadIdx.x;
    int wid = tid >> 5;
    int lane = tid & 31;
    int wrow = wid >> 1;              // 0..3
    int wcol = wid & 1;               // 0..1
    int row0 = blockIdx.x * MROWS;

    int tiles[3];
    tiles[0] = wrow;
    tiles[1] = wrow + 4;
    tiles[2] = wrow + 8;              // valid only for wrow<2
    bool has3 = (wrow < 2);

    // pre-sync prologue: layer-0 weight copy + biases
    issue_b_copy(sb, 0, tid);

    if (tid < 128) {
        float* bia = reinterpret_cast<float*>(smem + SBIAS);
        bia[tid] = b1[tid];
        bia[128 + tid] = b2[tid];
        bia[256 + tid] = b3[tid];
    }

    // wait for edge kernel's atomics into g_node
    cudaGridDependencySynchronize();

    // First-layer A: fp32 g_node -> fp16 hi/lo, padded [row][k] layout.
    for (int i = tid; i < MROWS * 32; i += 256) {
        int r = i >> 5, c4 = i & 31;
        int gr = row0 + r;
        float4 v = make_float4(0.f, 0.f, 0.f, 0.f);
        if (gr < natoms)
            v = __ldcs(&reinterpret_cast<const float4*>(&g_node[(long long)gr * EMB])[c4]);
        __half hx = __float2half_rn(v.x), hy = __float2half_rn(v.y);
        __half hz = __float2half_rn(v.z), hw = __float2half_rn(v.w);
        uint2 hp, lp;
        __half2 t;
        t.x = hx; t.y = hy; hp.x = *reinterpret_cast<uint32_t*>(&t);
        t.x = hz; t.y = hw; hp.y = *reinterpret_cast<uint32_t*>(&t);
        lp.x = pack_h2(v.x - __half2float(hx), v.y - __half2float(hy));
        lp.y = pack_h2(v.z - __half2float(hz), v.w - __half2float(hw));
        *reinterpret_cast<uint2*>(smem + SA_HI + r * (AP * 2) + c4 * 8) = hp;
        *reinterpret_cast<uint2*>(smem + SA_LO + r * (AP * 2) + c4 * 8) = lp;
    }

    uint32_t a_lane = (uint32_t)((lane & 15) * (AP * 2) + ((lane >> 4) * 8) * 2);
    uint32_t aH = sb + SA_HI + a_lane;
    uint32_t aL = sb + SA_LO + a_lane;
    uint32_t b_row = (uint32_t)(((lane >> 4) & 1) * 8 + (lane & 7));
    uint32_t b_k   = (uint32_t)(((lane >> 3) & 1) * 8);
    uint32_t b_off = (uint32_t)((wcol * 64 + b_row) * (AP * 2) + b_k * 2);
    uint32_t bB = sb + SB + b_off;

    const float* bias_all = reinterpret_cast<const float*>(smem + SBIAS);
    int g = lane >> 2;
    int t2 = (lane & 3) * 2;

    float acc[3][8][4];

    cp_async_wait0();
    __syncthreads();   // A + B(0) visible to all warps

    for (int layer = 0; layer < 4; layer++) {
        if (has3) layer_compute<3>(aH, aL, bB, tiles, acc);
        else      layer_compute<2>(aH, aL, bB, tiles, acc);

        __syncthreads();   // all A and B reads done -> safe to overwrite both

        if (layer < 3) {
            issue_b_copy(sb, layer + 1, tid);
            const float* bia = bias_all + layer * 128;
            if (has3) layer_epilogue_act<3>(smem, bia, tiles, acc, wcol, g, t2);
            else      layer_epilogue_act<2>(smem, bia, tiles, acc, wcol, g, t2);
            cp_async_wait0();
            __syncthreads();   // A(next) + B(next) visible
        } else {
            if (has3) layer_epilogue_out<3>(out, tiles, acc, row0, natoms, wcol, g, t2);
            else      layer_epilogue_out<2>(out, tiles, acc, row0, natoms, wcol, g, t2);
        }
    }
}

// ---------------------------------------------------------------------------
extern "C" void kernel_launch(void* const* d_in, const int* in_sizes, int n_in,
                              void* d_out, int out_size)
{
    const float* m_ji  = (const float*)d_in[0];
    const float* e_rbf = (const float*)d_in[1];
    const int*   nbr   = (const int*)d_in[2];

    int base = (n_in >= 12 && in_sizes[3] < 16) ? 4 : 3;
    const float* W_edge = (const float*)d_in[base + 0];
    const float* W1 = (const float*)d_in[base + 1];
    const float* b1 = (const float*)d_in[base + 2];
    const float* W2 = (const float*)d_in[base + 3];
    const float* b2 = (const float*)d_in[base + 4];
    const float* W3 = (const float*)d_in[base + 5];
    const float* b3 = (const float*)d_in[base + 6];
    const float* W4 = (const float*)d_in[base + 7];

    int E = in_sizes[1] / 6;
    int natoms = out_size / EMB;
    if (natoms > MAX_ATOMS) natoms = MAX_ATOMS;
    float* out = (float*)d_out;

    // setup: zero + weight prep + dtype detect
    int n4 = natoms * EMB / 4;
    setup_kernel<<<257, 256>>>(W1, W2, W3, W4, nbr, 2 * E, n4);

    cudaLaunchAttribute pdl[1];
    pdl[0].id = cudaLaunchAttributeProgrammaticStreamSerialization;
    pdl[0].val.programmaticStreamSerializationAllowed = 1;

    // edge pass (PDL-dependent on setup)
    {
        int warps = (E + 3) / 4;
        int eblocks = (warps + 7) / 8;
        cudaLaunchConfig_t cfg = {};
        cfg.gridDim = dim3((unsigned)eblocks, 1, 1);
        cfg.blockDim = dim3(256, 1, 1);
        cfg.dynamicSmemBytes = 0;
        cfg.stream = 0;
        cfg.attrs = pdl;
        cfg.numAttrs = 1;
        cudaLaunchKernelEx(&cfg, edge_kernel, m_ji, e_rbf, nbr, W_edge, E);
    }

    // MLP (PDL-dependent on edge): single wave of 125 CTAs
    cudaFuncSetAttribute(mlp_kernel, cudaFuncAttributeMaxDynamicSharedMemorySize, SMEM_TOTAL);
    {
        int mlp_blocks = (natoms + MROWS - 1) / MROWS;
        cudaLaunchConfig_t cfg = {};
        cfg.gridDim = dim3((unsigned)mlp_blocks, 1, 1);
        cfg.blockDim = dim3(256, 1, 1);
        cfg.dynamicSmemBytes = SMEM_TOTAL;
        cfg.stream = 0;
        cfg.attrs = pdl;
        cfg.numAttrs = 1;
        cudaLaunchKernelEx(&cfg, mlp_kernel, b1, b2, b3, out, natoms);
    }
}

// round 12
// speedup vs baseline: 1.1207x; 1.0762x over previous
#include <cuda_runtime.h>
#include <cuda_bf16.h>
#include <cuda_fp16.h>
#include <cstdint>

#define EMB 128
#define MAX_ATOMS 20000
#define AP 136                      // padded row stride (fp16 elems) = 272 B
#define MROWS 160                   // rows per MLP CTA (10 m16 tiles)

// ---------------------------------------------------------------------------
__device__ __align__(16) float g_node[MAX_ATOMS * EMB];     // segment-sum acc
__device__ __align__(16) __half g_wh[4 * 128 * AP];         // [layer][n*AP+k] fp16 weights
__device__ int g_is64;

// ---------------------------------------------------------------------------
__device__ __forceinline__ uint32_t smem_to_u32(const void* p) {
    uint32_t a;
    asm("{ .reg .u64 t; cvta.to.shared.u64 t, %1; cvt.u32.u64 %0, t; }" : "=r"(a) : "l"(p));
    return a;
}

__device__ __forceinline__ void ldsm_x4(uint32_t addr, uint32_t r[4]) {
    asm volatile("ldmatrix.sync.aligned.m8n8.x4.shared.b16 {%0,%1,%2,%3}, [%4];"
                 : "=r"(r[0]), "=r"(r[1]), "=r"(r[2]), "=r"(r[3]) : "r"(addr));
}

__device__ __forceinline__ void mma16816h(float d[4], const uint32_t a[4],
                                          uint32_t b0, uint32_t b1) {
    asm volatile(
        "mma.sync.aligned.m16n8k16.row.col.f32.f16.f16.f32 "
        "{%0,%1,%2,%3}, {%4,%5,%6,%7}, {%8,%9}, {%0,%1,%2,%3};"
        : "+f"(d[0]), "+f"(d[1]), "+f"(d[2]), "+f"(d[3])
        : "r"(a[0]), "r"(a[1]), "r"(a[2]), "r"(a[3]), "r"(b0), "r"(b1));
}

__device__ __forceinline__ uint32_t pack_h2(float x, float y) {
    __half2 v;
    v.x = __float2half_rn(x);
    v.y = __float2half_rn(y);
    return *reinterpret_cast<uint32_t*>(&v);
}

__device__ __forceinline__ void cp_async16(uint32_t smem_addr, const void* gptr) {
    asm volatile("cp.async.cg.shared.global [%0], [%1], 16;"
                 :: "r"(smem_addr), "l"(gptr));
}
__device__ __forceinline__ void cp_async_commit() {
    asm volatile("cp.async.commit_group;" ::: "memory");
}
__device__ __forceinline__ void cp_async_wait0() {
    asm volatile("cp.async.wait_group 0;" ::: "memory");
}

// fast swish: x * sigmoid(x) via EX2 + RCP (no IEEE div)
__device__ __forceinline__ float fast_swish(float x) {
    float e = __expf(-x);
    return __fdividef(x, 1.0f + e);
}

// ---------------------------------------------------------------------------
// Fused setup, grid-stride (257 blocks):
//   blocks 0..255 : weight prep (fp16, 1 elem/thread) + grid-stride zero
//   block 256     : dtype detect + tail of zero loop
// ---------------------------------------------------------------------------
__global__ void setup_kernel(const float* __restrict__ W1, const float* __restrict__ W2,
                             const float* __restrict__ W3, const float* __restrict__ W4,
                             const int* __restrict__ nbr, int n_words, int n4)
{
    int b = blockIdx.x;
    int tid = threadIdx.x;

    float4* gz = reinterpret_cast<float4*>(g_node);
    for (int i = b * 256 + tid; i < n4; i += 257 * 256)
        gz[i] = make_float4(0.f, 0.f, 0.f, 0.f);

    if (b < 256) {
        int idx = b * 256 + tid;           // 65536 elements
        int l = idx >> 14;
        int e = idx & 16383;
        int k = e >> 7, n = e & 127;       // W row-major: W[k][n]
        const float* W = (l == 0) ? W1 : (l == 1) ? W2 : (l == 2) ? W3 : W4;
        g_wh[l * (128 * AP) + n * AP + k] = __float2half_rn(W[e]);
        return;
    }
    __shared__ int any;
    if (tid == 0) any = 0;
    __syncthreads();
    int found = 0;
    for (int i = tid; i < 2048; i += blockDim.x) {
        int idx = 2 * i + 1;
        if (idx < n_words && nbr[idx] != 0) found = 1;
    }
    if (found) atomicOr(&any, 1);
    __syncthreads();
    if (tid == 0) g_is64 = (any == 0) ? 1 : 0;
}

// ---------------------------------------------------------------------------
// Edge pass (unchanged): one warp = 4 edges, PDL prologue split.
// ---------------------------------------------------------------------------
__global__ void __launch_bounds__(256, 5) edge_kernel(
    const float* __restrict__ m_ji,
    const float* __restrict__ e_rbf,
    const int*   __restrict__ nbr,
    const float* __restrict__ W_edge,
    int E)
{
    __shared__ float sWe[6 * 128];
    int tid = threadIdx.x;
    for (int i = tid; i < 6 * 128; i += blockDim.x) sWe[i] = W_edge[i];
    __syncthreads();

    int warp = (int)((blockIdx.x * (long long)blockDim.x + tid) >> 5);
    int lane = tid & 31;
    long long e0 = (long long)warp * 4;
    if (e0 >= E) return;

    float rbf = 0.0f;
    if (lane < 24 && e0 * 6 + lane < (long long)E * 6)
        rbf = __ldcs(&e_rbf[e0 * 6 + lane]);

    const float4* we4 = reinterpret_cast<const float4*>(sWe);
    float4 wv[6];
#pragma unroll
    for (int r = 0; r < 6; r++) wv[r] = we4[r * 32 + lane];

    cudaGridDependencySynchronize();

    int is64 = g_is64;
    int d = 0;
    if (lane < 4 && e0 + lane < E)
        d = is64 ? __ldcs(&nbr[(e0 + lane) * 4 + 2]) : __ldcs(&nbr[(e0 + lane) * 2 + 1]);

#pragma unroll
    for (int j = 0; j < 4; j++) {
        if (e0 + j >= E) break;
        float4 m = __ldcs(&reinterpret_cast<const float4*>(m_ji + (e0 + j) * EMB)[lane]);
        float4 w = make_float4(0.f, 0.f, 0.f, 0.f);
#pragma unroll
        for (int r = 0; r < 6; r++) {
            float c = __shfl_sync(0xffffffffu, rbf, j * 6 + r);
            w.x = fmaf(c, wv[r].x, w.x);
            w.y = fmaf(c, wv[r].y, w.y);
            w.z = fmaf(c, wv[r].z, w.z);
            w.w = fmaf(c, wv[r].w, w.w);
        }
        float4 o = make_float4(w.x * m.x, w.y * m.y, w.z * m.z, w.w * m.w);
        int dj = __shfl_sync(0xffffffffu, d, j);
        atomicAdd(reinterpret_cast<float4*>(&g_node[(long long)dj * EMB + lane * 4]), o);
    }
}

// ---------------------------------------------------------------------------
// MLP: pure fp16 mma.sync (single-term A and B). 1 MMA per tile-kstep.
// 256 thr, 8 warps, 160 rows/CTA, 125 CTAs single wave.
// smem: A(43520) B(34816) bias(1536)
// ---------------------------------------------------------------------------
#define SA    0
#define SB    43520
#define SBIAS 78336
#define SMEM_TOTAL (78336 + 1536)
#define B_CHUNKS 2176               // 34816 B / 16 = float4 count for one buffer

__device__ __forceinline__ void issue_b_copy(uint32_t sb, int layer, int tid) {
    const char* src = reinterpret_cast<const char*>(g_wh + layer * (128 * AP));
#pragma unroll 4
    for (int i = tid; i < B_CHUNKS; i += 256)
        cp_async16(sb + SB + i * 16, src + i * 16);
    cp_async_commit();
}

template <int MT>
__device__ __forceinline__ void layer_compute(
    uint32_t aA, uint32_t bB,
    const int* tiles, float acc[][8][4])
{
#pragma unroll
    for (int mt = 0; mt < MT; mt++)
#pragma unroll
        for (int nt = 0; nt < 8; nt++)
#pragma unroll
            for (int q = 0; q < 4; q++) acc[mt][nt][q] = 0.0f;

#pragma unroll
    for (int k0 = 0; k0 < 128; k0 += 16) {
        uint32_t ah[MT][4];
#pragma unroll
        for (int mt = 0; mt < MT; mt++) {
            uint32_t toff = (uint32_t)(tiles[mt] * 16 * (AP * 2)) + k0 * 2;
            ldsm_x4(aA + toff, ah[mt]);
        }
#pragma unroll
        for (int nt2 = 0; nt2 < 4; nt2++) {
            uint32_t bh[4];
            ldsm_x4(bB + nt2 * 16 * (AP * 2) + k0 * 2, bh);
#pragma unroll
            for (int nt = 0; nt < 2; nt++) {
                int nti = nt2 * 2 + nt;
#pragma unroll
                for (int mt = 0; mt < MT; mt++)
                    mma16816h(acc[mt][nti], ah[mt], bh[nt * 2], bh[nt * 2 + 1]);
            }
        }
    }
}

template <int MT>
__device__ __forceinline__ void layer_epilogue_act(
    char* smem, const float* bia, const int* tiles, float acc[][8][4],
    int wcol, int g, int t2)
{
#pragma unroll
    for (int mt = 0; mt < MT; mt++) {
        int rA = tiles[mt] * 16 + g;
        int rB = rA + 8;
#pragma unroll
        for (int nt = 0; nt < 8; nt++) {
            int col = wcol * 64 + nt * 8 + t2;
            float b0 = bia[col], b1v = bia[col + 1];
            float s0 = fast_swish(acc[mt][nt][0] + b0);
            float s1 = fast_swish(acc[mt][nt][1] + b1v);
            float s2 = fast_swish(acc[mt][nt][2] + b0);
            float s3 = fast_swish(acc[mt][nt][3] + b1v);
            *reinterpret_cast<uint32_t*>(smem + SA + rA * (AP * 2) + col * 2) =
                pack_h2(s0, s1);
            *reinterpret_cast<uint32_t*>(smem + SA + rB * (AP * 2) + col * 2) =
                pack_h2(s2, s3);
        }
    }
}

template <int MT>
__device__ __forceinline__ void layer_epilogue_out(
    float* __restrict__ out, const int* tiles, float acc[][8][4],
    int row0, int natoms, int wcol, int g, int t2)
{
#pragma unroll
    for (int mt = 0; mt < MT; mt++) {
        int rA = row0 + tiles[mt] * 16 + g;
        int rB = rA + 8;
#pragma unroll
        for (int nt = 0; nt < 8; nt++) {
            int col = wcol * 64 + nt * 8 + t2;
            if (rA < natoms)
                *reinterpret_cast<float2*>(&out[(long long)rA * EMB + col]) =
                    make_float2(acc[mt][nt][0], acc[mt][nt][1]);
            if (rB < natoms)
                *reinterpret_cast<float2*>(&out[(long long)rB * EMB + col]) =
                    make_float2(acc[mt][nt][2], acc[mt][nt][3]);
        }
    }
}

__global__ void __launch_bounds__(256, 1) mlp_kernel(
    const float* __restrict__ b1, const float* __restrict__ b2,
    const float* __restrict__ b3,
    float* __restrict__ out, int natoms)
{
    extern __shared__ char smem[];
    uint32_t sb = smem_to_u32(smem);
    int tid = threadIdx.x;
    int wid = tid >> 5;
    int lane = tid & 31;
    int wrow = wid >> 1;              // 0..3
    int wcol = wid & 1;               // 0..1
    int row0 = blockIdx.x * MROWS;

    int tiles[3];
    tiles[0] = wrow;
    tiles[1] = wrow + 4;
    tiles[2] = wrow + 8;              // valid only for wrow<2
    bool has3 = (wrow < 2);

    // pre-sync prologue: layer-0 weight copy + biases
    issue_b_copy(sb, 0, tid);

    if (tid < 128) {
        float* bia = reinterpret_cast<float*>(smem + SBIAS);
        bia[tid] = b1[tid];
        bia[128 + tid] = b2[tid];
        bia[256 + tid] = b3[tid];
    }

    // wait for edge kernel's atomics into g_node
    cudaGridDependencySynchronize();

    // First-layer A: fp32 g_node -> fp16, padded [row][k] layout.
    for (int i = tid; i < MROWS * 32; i += 256) {
        int r = i >> 5, c4 = i & 31;
        int gr = row0 + r;
        float4 v = make_float4(0.f, 0.f, 0.f, 0.f);
        if (gr < natoms)
            v = __ldcs(&reinterpret_cast<const float4*>(&g_node[(long long)gr * EMB])[c4]);
        uint2 hp;
        hp.x = pack_h2(v.x, v.y);
        hp.y = pack_h2(v.z, v.w);
        *reinterpret_cast<uint2*>(smem + SA + r * (AP * 2) + c4 * 8) = hp;
    }

    uint32_t a_lane = (uint32_t)((lane & 15) * (AP * 2) + ((lane >> 4) * 8) * 2);
    uint32_t aA = sb + SA + a_lane;
    uint32_t b_row = (uint32_t)(((lane >> 4) & 1) * 8 + (lane & 7));
    uint32_t b_k   = (uint32_t)(((lane >> 3) & 1) * 8);
    uint32_t b_off = (uint32_t)((wcol * 64 + b_row) * (AP * 2) + b_k * 2);
    uint32_t bB = sb + SB + b_off;

    const float* bias_all = reinterpret_cast<const float*>(smem + SBIAS);
    int g = lane >> 2;
    int t2 = (lane & 3) * 2;

    float acc[3][8][4];

    cp_async_wait0();
    __syncthreads();   // A + B(0) visible to all warps

    for (int layer = 0; layer < 4; layer++) {
        if (has3) layer_compute<3>(aA, bB, tiles, acc);
        else      layer_compute<2>(aA, bB, tiles, acc);

        __syncthreads();   // all A and B reads done -> safe to overwrite both

        if (layer < 3) {
            issue_b_copy(sb, layer + 1, tid);
            const float* bia = bias_all + layer * 128;
            if (has3) layer_epilogue_act<3>(smem, bia, tiles, acc, wcol, g, t2);
            else      layer_epilogue_act<2>(smem, bia, tiles, acc, wcol, g, t2);
            cp_async_wait0();
            __syncthreads();   // A(next) + B(next) visible
        } else {
            if (has3) layer_epilogue_out<3>(out, tiles, acc, row0, natoms, wcol, g, t2);
            else      layer_epilogue_out<2>(out, tiles, acc, row0, natoms, wcol, g, t2);
        }
    }
}

// ---------------------------------------------------------------------------
extern "C" void kernel_launch(void* const* d_in, const int* in_sizes, int n_in,
                              void* d_out, int out_size)
{
    const float* m_ji  = (const float*)d_in[0];
    const float* e_rbf = (const float*)d_in[1];
    const int*   nbr   = (const int*)d_in[2];

    int base = (n_in >= 12 && in_sizes[3] < 16) ? 4 : 3;
    const float* W_edge = (const float*)d_in[base + 0];
    const float* W1 = (const float*)d_in[base + 1];
    const float* b1 = (const float*)d_in[base + 2];
    const float* W2 = (const float*)d_in[base + 3];
    const float* b2 = (const float*)d_in[base + 4];
    const float* W3 = (const float*)d_in[base + 5];
    const float* b3 = (const float*)d_in[base + 6];
    const float* W4 = (const float*)d_in[base + 7];

    int E = in_sizes[1] / 6;
    int natoms = out_size / EMB;
    if (natoms > MAX_ATOMS) natoms = MAX_ATOMS;
    float* out = (float*)d_out;

    // setup: zero + weight prep + dtype detect
    int n4 = natoms * EMB / 4;
    setup_kernel<<<257, 256>>>(W1, W2, W3, W4, nbr, 2 * E, n4);

    cudaLaunchAttribute pdl[1];
    pdl[0].id = cudaLaunchAttributeProgrammaticStreamSerialization;
    pdl[0].val.programmaticStreamSerializationAllowed = 1;

    // edge pass (PDL-dependent on setup)
    {
        int warps = (E + 3) / 4;
        int eblocks = (warps + 7) / 8;
        cudaLaunchConfig_t cfg = {};
        cfg.gridDim = dim3((unsigned)eblocks, 1, 1);
        cfg.blockDim = dim3(256, 1, 1);
        cfg.dynamicSmemBytes = 0;
        cfg.stream = 0;
        cfg.attrs = pdl;
        cfg.numAttrs = 1;
        cudaLaunchKernelEx(&cfg, edge_kernel, m_ji, e_rbf, nbr, W_edge, E);
    }

    // MLP (PDL-dependent on edge): single wave of 125 CTAs
    cudaFuncSetAttribute(mlp_kernel, cudaFuncAttributeMaxDynamicSharedMemorySize, SMEM_TOTAL);
    {
        int mlp_blocks = (natoms + MROWS - 1) / MROWS;
        cudaLaunchConfig_t cfg = {};
        cfg.gridDim = dim3((unsigned)mlp_blocks, 1, 1);
        cfg.blockDim = dim3(256, 1, 1);
        cfg.dynamicSmemBytes = SMEM_TOTAL;
        cfg.stream = 0;
        cfg.attrs = pdl;
        cfg.numAttrs = 1;
        cudaLaunchKernelEx(&cfg, mlp_kernel, b1, b2, b3, out, natoms);
    }
}

// round 13
// speedup vs baseline: 1.1283x; 1.0068x over previous
#include <cuda_runtime.h>
#include <cuda_bf16.h>
#include <cuda_fp16.h>
#include <cstdint>

#define EMB 128
#define MAX_ATOMS 20000
#define AP 136                      // padded row stride (fp16 elems) = 272 B
#define MROWS 96                    // rows per MLP CTA (6 m16 tiles), 2 CTAs/SM

// ---------------------------------------------------------------------------
__device__ __align__(16) float g_node[MAX_ATOMS * EMB];     // segment-sum acc
__device__ __align__(16) __half g_wh[4 * 128 * AP];         // [layer][n*AP+k] fp16 weights
__device__ int g_is64;

// ---------------------------------------------------------------------------
__device__ __forceinline__ uint32_t smem_to_u32(const void* p) {
    uint32_t a;
    asm("{ .reg .u64 t; cvta.to.shared.u64 t, %1; cvt.u32.u64 %0, t; }" : "=r"(a) : "l"(p));
    return a;
}

__device__ __forceinline__ void ldsm_x4(uint32_t addr, uint32_t r[4]) {
    asm volatile("ldmatrix.sync.aligned.m8n8.x4.shared.b16 {%0,%1,%2,%3}, [%4];"
                 : "=r"(r[0]), "=r"(r[1]), "=r"(r[2]), "=r"(r[3]) : "r"(addr));
}

__device__ __forceinline__ void mma16816h(float d[4], const uint32_t a[4],
                                          uint32_t b0, uint32_t b1) {
    asm volatile(
        "mma.sync.aligned.m16n8k16.row.col.f32.f16.f16.f32 "
        "{%0,%1,%2,%3}, {%4,%5,%6,%7}, {%8,%9}, {%0,%1,%2,%3};"
        : "+f"(d[0]), "+f"(d[1]), "+f"(d[2]), "+f"(d[3])
        : "r"(a[0]), "r"(a[1]), "r"(a[2]), "r"(a[3]), "r"(b0), "r"(b1));
}

__device__ __forceinline__ uint32_t pack_h2(float x, float y) {
    __half2 v;
    v.x = __float2half_rn(x);
    v.y = __float2half_rn(y);
    return *reinterpret_cast<uint32_t*>(&v);
}

__device__ __forceinline__ void cp_async16(uint32_t smem_addr, const void* gptr) {
    asm volatile("cp.async.cg.shared.global [%0], [%1], 16;"
                 :: "r"(smem_addr), "l"(gptr));
}
__device__ __forceinline__ void cp_async_commit() {
    asm volatile("cp.async.commit_group;" ::: "memory");
}
__device__ __forceinline__ void cp_async_wait0() {
    asm volatile("cp.async.wait_group 0;" ::: "memory");
}

// fast swish: x * sigmoid(x) via EX2 + RCP (no IEEE div)
__device__ __forceinline__ float fast_swish(float x) {
    float e = __expf(-x);
    return __fdividef(x, 1.0f + e);
}

// ---------------------------------------------------------------------------
// Fused setup, grid-stride (257 blocks):
//   blocks 0..255 : weight prep (fp16, 1 elem/thread) + grid-stride zero
//   block 256     : dtype detect + tail of zero loop
// ---------------------------------------------------------------------------
__global__ void setup_kernel(const float* __restrict__ W1, const float* __restrict__ W2,
                             const float* __restrict__ W3, const float* __restrict__ W4,
                             const int* __restrict__ nbr, int n_words, int n4)
{
    int b = blockIdx.x;
    int tid = threadIdx.x;

    float4* gz = reinterpret_cast<float4*>(g_node);
    for (int i = b * 256 + tid; i < n4; i += 257 * 256)
        gz[i] = make_float4(0.f, 0.f, 0.f, 0.f);

    if (b < 256) {
        int idx = b * 256 + tid;           // 65536 elements
        int l = idx >> 14;
        int e = idx & 16383;
        int k = e >> 7, n = e & 127;       // W row-major: W[k][n]
        const float* W = (l == 0) ? W1 : (l == 1) ? W2 : (l == 2) ? W3 : W4;
        g_wh[l * (128 * AP) + n * AP + k] = __float2half_rn(W[e]);
        return;
    }
    __shared__ int any;
    if (tid == 0) any = 0;
    __syncthreads();
    int found = 0;
    for (int i = tid; i < 2048; i += blockDim.x) {
        int idx = 2 * i + 1;
        if (idx < n_words && nbr[idx] != 0) found = 1;
    }
    if (found) atomicOr(&any, 1);
    __syncthreads();
    if (tid == 0) g_is64 = (any == 0) ? 1 : 0;
}

// ---------------------------------------------------------------------------
// Edge pass (unchanged): one warp = 4 edges, PDL prologue split.
// ---------------------------------------------------------------------------
__global__ void __launch_bounds__(256, 5) edge_kernel(
    const float* __restrict__ m_ji,
    const float* __restrict__ e_rbf,
    const int*   __restrict__ nbr,
    const float* __restrict__ W_edge,
    int E)
{
    __shared__ float sWe[6 * 128];
    int tid = threadIdx.x;
    for (int i = tid; i < 6 * 128; i += blockDim.x) sWe[i] = W_edge[i];
    __syncthreads();

    int warp = (int)((blockIdx.x * (long long)blockDim.x + tid) >> 5);
    int lane = tid & 31;
    long long e0 = (long long)warp * 4;
    if (e0 >= E) return;

    float rbf = 0.0f;
    if (lane < 24 && e0 * 6 + lane < (long long)E * 6)
        rbf = __ldcs(&e_rbf[e0 * 6 + lane]);

    const float4* we4 = reinterpret_cast<const float4*>(sWe);
    float4 wv[6];
#pragma unroll
    for (int r = 0; r < 6; r++) wv[r] = we4[r * 32 + lane];

    cudaGridDependencySynchronize();

    int is64 = g_is64;
    int d = 0;
    if (lane < 4 && e0 + lane < E)
        d = is64 ? __ldcs(&nbr[(e0 + lane) * 4 + 2]) : __ldcs(&nbr[(e0 + lane) * 2 + 1]);

#pragma unroll
    for (int j = 0; j < 4; j++) {
        if (e0 + j >= E) break;
        float4 m = __ldcs(&reinterpret_cast<const float4*>(m_ji + (e0 + j) * EMB)[lane]);
        float4 w = make_float4(0.f, 0.f, 0.f, 0.f);
#pragma unroll
        for (int r = 0; r < 6; r++) {
            float c = __shfl_sync(0xffffffffu, rbf, j * 6 + r);
            w.x = fmaf(c, wv[r].x, w.x);
            w.y = fmaf(c, wv[r].y, w.y);
            w.z = fmaf(c, wv[r].z, w.z);
            w.w = fmaf(c, wv[r].w, w.w);
        }
        float4 o = make_float4(w.x * m.x, w.y * m.y, w.z * m.z, w.w * m.w);
        int dj = __shfl_sync(0xffffffffu, d, j);
        atomicAdd(reinterpret_cast<float4*>(&g_node[(long long)dj * EMB + lane * 4]), o);
    }
}

// ---------------------------------------------------------------------------
// MLP: pure fp16 mma.sync, 96 rows/CTA (6 m16 tiles), 2 CTAs/SM, 209 CTAs
// in one wave across all 148 SMs. 256 thr, 8 warps.
// Warp wid: wrow=wid>>1 (tiles {wrow, wrow+4 if wrow<2}), wcol=wid&1.
// smem: A(26112) B(34816) bias(1536) = 62464 B per CTA
// ---------------------------------------------------------------------------
#define SA    0
#define SB    26112
#define SBIAS 60928
#define SMEM_TOTAL (60928 + 1536)
#define B_CHUNKS 2176               // 34816 B / 16 = float4 count for one buffer

__device__ __forceinline__ void issue_b_copy(uint32_t sb, int layer, int tid) {
    const char* src = reinterpret_cast<const char*>(g_wh + layer * (128 * AP));
#pragma unroll 4
    for (int i = tid; i < B_CHUNKS; i += 256)
        cp_async16(sb + SB + i * 16, src + i * 16);
    cp_async_commit();
}

template <int MT>
__device__ __forceinline__ void layer_compute(
    uint32_t aA, uint32_t bB,
    const int* tiles, float acc[][8][4])
{
#pragma unroll
    for (int mt = 0; mt < MT; mt++)
#pragma unroll
        for (int nt = 0; nt < 8; nt++)
#pragma unroll
            for (int q = 0; q < 4; q++) acc[mt][nt][q] = 0.0f;

#pragma unroll
    for (int k0 = 0; k0 < 128; k0 += 16) {
        uint32_t ah[MT][4];
#pragma unroll
        for (int mt = 0; mt < MT; mt++) {
            uint32_t toff = (uint32_t)(tiles[mt] * 16 * (AP * 2)) + k0 * 2;
            ldsm_x4(aA + toff, ah[mt]);
        }
#pragma unroll
        for (int nt2 = 0; nt2 < 4; nt2++) {
            uint32_t bh[4];
            ldsm_x4(bB + nt2 * 16 * (AP * 2) + k0 * 2, bh);
#pragma unroll
            for (int nt = 0; nt < 2; nt++) {
                int nti = nt2 * 2 + nt;
#pragma unroll
                for (int mt = 0; mt < MT; mt++)
                    mma16816h(acc[mt][nti], ah[mt], bh[nt * 2], bh[nt * 2 + 1]);
            }
        }
    }
}

template <int MT>
__device__ __forceinline__ void layer_epilogue_act(
    char* smem, const float* bia, const int* tiles, float acc[][8][4],
    int wcol, int g, int t2)
{
#pragma unroll
    for (int mt = 0; mt < MT; mt++) {
        int rA = tiles[mt] * 16 + g;
        int rB = rA + 8;
#pragma unroll
        for (int nt = 0; nt < 8; nt++) {
            int col = wcol * 64 + nt * 8 + t2;
            float b0 = bia[col], b1v = bia[col + 1];
            float s0 = fast_swish(acc[mt][nt][0] + b0);
            float s1 = fast_swish(acc[mt][nt][1] + b1v);
            float s2 = fast_swish(acc[mt][nt][2] + b0);
            float s3 = fast_swish(acc[mt][nt][3] + b1v);
            *reinterpret_cast<uint32_t*>(smem + SA + rA * (AP * 2) + col * 2) =
                pack_h2(s0, s1);
            *reinterpret_cast<uint32_t*>(smem + SA + rB * (AP * 2) + col * 2) =
                pack_h2(s2, s3);
        }
    }
}

template <int MT>
__device__ __forceinline__ void layer_epilogue_out(
    float* __restrict__ out, const int* tiles, float acc[][8][4],
    int row0, int natoms, int wcol, int g, int t2)
{
#pragma unroll
    for (int mt = 0; mt < MT; mt++) {
        int rA = row0 + tiles[mt] * 16 + g;
        int rB = rA + 8;
#pragma unroll
        for (int nt = 0; nt < 8; nt++) {
            int col = wcol * 64 + nt * 8 + t2;
            if (rA < natoms)
                *reinterpret_cast<float2*>(&out[(long long)rA * EMB + col]) =
                    make_float2(acc[mt][nt][0], acc[mt][nt][1]);
            if (rB < natoms)
                *reinterpret_cast<float2*>(&out[(long long)rB * EMB + col]) =
                    make_float2(acc[mt][nt][2], acc[mt][nt][3]);
        }
    }
}

__global__ void __launch_bounds__(256, 2) mlp_kernel(
    const float* __restrict__ b1, const float* __restrict__ b2,
    const float* __restrict__ b3,
    float* __restrict__ out, int natoms)
{
    extern __shared__ char smem[];
    uint32_t sb = smem_to_u32(smem);
    int tid = threadIdx.x;
    int wid = tid >> 5;
    int lane = tid & 31;
    int wrow = wid >> 1;              // 0..3
    int wcol = wid & 1;               // 0..1
    int row0 = blockIdx.x * MROWS;

    // 6 m16-tiles: row-groups 0,1 take {wrow, wrow+4}; groups 2,3 take {wrow}
    int tiles[2];
    tiles[0] = wrow;
    tiles[1] = wrow + 4;              // valid only for wrow<2
    bool has2 = (wrow < 2);

    // pre-sync prologue: layer-0 weight copy + biases
    issue_b_copy(sb, 0, tid);

    if (tid < 128) {
        float* bia = reinterpret_cast<float*>(smem + SBIAS);
        bia[tid] = b1[tid];
        bia[128 + tid] = b2[tid];
        bia[256 + tid] = b3[tid];
    }

    // wait for edge kernel's atomics into g_node
    cudaGridDependencySynchronize();

    // First-layer A: fp32 g_node -> fp16, padded [row][k] layout.
    for (int i = tid; i < MROWS * 32; i += 256) {
        int r = i >> 5, c4 = i & 31;
        int gr = row0 + r;
        float4 v = make_float4(0.f, 0.f, 0.f, 0.f);
        if (gr < natoms)
            v = __ldcs(&reinterpret_cast<const float4*>(&g_node[(long long)gr * EMB])[c4]);
        uint2 hp;
        hp.x = pack_h2(v.x, v.y);
        hp.y = pack_h2(v.z, v.w);
        *reinterpret_cast<uint2*>(smem + SA + r * (AP * 2) + c4 * 8) = hp;
    }

    uint32_t a_lane = (uint32_t)((lane & 15) * (AP * 2) + ((lane >> 4) * 8) * 2);
    uint32_t aA = sb + SA + a_lane;
    uint32_t b_row = (uint32_t)(((lane >> 4) & 1) * 8 + (lane & 7));
    uint32_t b_k   = (uint32_t)(((lane >> 3) & 1) * 8);
    uint32_t b_off = (uint32_t)((wcol * 64 + b_row) * (AP * 2) + b_k * 2);
    uint32_t bB = sb + SB + b_off;

    const float* bias_all = reinterpret_cast<const float*>(smem + SBIAS);
    int g = lane >> 2;
    int t2 = (lane & 3) * 2;

    float acc[2][8][4];

    cp_async_wait0();
    __syncthreads();   // A + B(0) visible to all warps

    for (int layer = 0; layer < 4; layer++) {
        if (has2) layer_compute<2>(aA, bB, tiles, acc);
        else      layer_compute<1>(aA, bB, tiles, acc);

        __syncthreads();   // all A and B reads done -> safe to overwrite both

        if (layer < 3) {
            issue_b_copy(sb, layer + 1, tid);
            const float* bia = bias_all + layer * 128;
            if (has2) layer_epilogue_act<2>(smem, bia, tiles, acc, wcol, g, t2);
            else      layer_epilogue_act<1>(smem, bia, tiles, acc, wcol, g, t2);
            cp_async_wait0();
            __syncthreads();   // A(next) + B(next) visible
        } else {
            if (has2) layer_epilogue_out<2>(out, tiles, acc, row0, natoms, wcol, g, t2);
            else      layer_epilogue_out<1>(out, tiles, acc, row0, natoms, wcol, g, t2);
        }
    }
}

// ---------------------------------------------------------------------------
extern "C" void kernel_launch(void* const* d_in, const int* in_sizes, int n_in,
                              void* d_out, int out_size)
{
    const float* m_ji  = (const float*)d_in[0];
    const float* e_rbf = (const float*)d_in[1];
    const int*   nbr   = (const int*)d_in[2];

    int base = (n_in >= 12 && in_sizes[3] < 16) ? 4 : 3;
    const float* W_edge = (const float*)d_in[base + 0];
    const float* W1 = (const float*)d_in[base + 1];
    const float* b1 = (const float*)d_in[base + 2];
    const float* W2 = (const float*)d_in[base + 3];
    const float* b2 = (const float*)d_in[base + 4];
    const float* W3 = (const float*)d_in[base + 5];
    const float* b3 = (const float*)d_in[base + 6];
    const float* W4 = (const float*)d_in[base + 7];

    int E = in_sizes[1] / 6;
    int natoms = out_size / EMB;
    if (natoms > MAX_ATOMS) natoms = MAX_ATOMS;
    float* out = (float*)d_out;

    // setup: zero + weight prep + dtype detect
    int n4 = natoms * EMB / 4;
    setup_kernel<<<257, 256>>>(W1, W2, W3, W4, nbr, 2 * E, n4);

    cudaLaunchAttribute pdl[1];
    pdl[0].id = cudaLaunchAttributeProgrammaticStreamSerialization;
    pdl[0].val.programmaticStreamSerializationAllowed = 1;

    // edge pass (PDL-dependent on setup)
    {
        int warps = (E + 3) / 4;
        int eblocks = (warps + 7) / 8;
        cudaLaunchConfig_t cfg = {};
        cfg.gridDim = dim3((unsigned)eblocks, 1, 1);
        cfg.blockDim = dim3(256, 1, 1);
        cfg.dynamicSmemBytes = 0;
        cfg.stream = 0;
        cfg.attrs = pdl;
        cfg.numAttrs = 1;
        cudaLaunchKernelEx(&cfg, edge_kernel, m_ji, e_rbf, nbr, W_edge, E);
    }

    // MLP (PDL-dependent on edge): 209 CTAs, 2 CTAs/SM, single wave
    cudaFuncSetAttribute(mlp_kernel, cudaFuncAttributeMaxDynamicSharedMemorySize, SMEM_TOTAL);
    {
        int mlp_blocks = (natoms + MROWS - 1) / MROWS;
        cudaLaunchConfig_t cfg = {};
        cfg.gridDim = dim3((unsigned)mlp_blocks, 1, 1);
        cfg.blockDim = dim3(256, 1, 1);
        cfg.dynamicSmemBytes = SMEM_TOTAL;
        cfg.stream = 0;
        cfg.attrs = pdl;
        cfg.numAttrs = 1;
        cudaLaunchKernelEx(&cfg, mlp_kernel, b1, b2, b3, out, natoms);
    }
}

// round 14
// speedup vs baseline: 1.2048x; 1.0678x over previous
#include <cuda_runtime.h>
#include <cuda_bf16.h>
#include <cuda_fp16.h>
#include <cstdint>

#define EMB 128
#define MAX_ATOMS 20000
#define AP 136                      // padded row stride (fp16 elems) = 272 B
#define MROWS 96                    // rows per MLP CTA (6 m16 tiles), 2 CTAs/SM

// ---------------------------------------------------------------------------
__device__ __align__(16) float g_node[MAX_ATOMS * EMB];     // segment-sum acc
__device__ __align__(16) __half g_wh[4 * 128 * AP];         // [layer][n*AP+k] fp16 weights
__device__ int g_is64;

// ---------------------------------------------------------------------------
__device__ __forceinline__ uint32_t smem_to_u32(const void* p) {
    uint32_t a;
    asm("{ .reg .u64 t; cvta.to.shared.u64 t, %1; cvt.u32.u64 %0, t; }" : "=r"(a) : "l"(p));
    return a;
}

__device__ __forceinline__ void ldsm_x4(uint32_t addr, uint32_t r[4]) {
    asm volatile("ldmatrix.sync.aligned.m8n8.x4.shared.b16 {%0,%1,%2,%3}, [%4];"
                 : "=r"(r[0]), "=r"(r[1]), "=r"(r[2]), "=r"(r[3]) : "r"(addr));
}

__device__ __forceinline__ void mma16816h(float d[4], const uint32_t a[4],
                                          uint32_t b0, uint32_t b1) {
    asm volatile(
        "mma.sync.aligned.m16n8k16.row.col.f32.f16.f16.f32 "
        "{%0,%1,%2,%3}, {%4,%5,%6,%7}, {%8,%9}, {%0,%1,%2,%3};"
        : "+f"(d[0]), "+f"(d[1]), "+f"(d[2]), "+f"(d[3])
        : "r"(a[0]), "r"(a[1]), "r"(a[2]), "r"(a[3]), "r"(b0), "r"(b1));
}

__device__ __forceinline__ uint32_t pack_h2(float x, float y) {
    __half2 v;
    v.x = __float2half_rn(x);
    v.y = __float2half_rn(y);
    return *reinterpret_cast<uint32_t*>(&v);
}

__device__ __forceinline__ void cp_async16(uint32_t smem_addr, const void* gptr) {
    asm volatile("cp.async.cg.shared.global [%0], [%1], 16;"
                 :: "r"(smem_addr), "l"(gptr));
}
__device__ __forceinline__ void cp_async_commit() {
    asm volatile("cp.async.commit_group;" ::: "memory");
}
__device__ __forceinline__ void cp_async_wait0() {
    asm volatile("cp.async.wait_group 0;" ::: "memory");
}

// fast swish: x * sigmoid(x) via EX2 + RCP (no IEEE div)
__device__ __forceinline__ float fast_swish(float x) {
    float e = __expf(-x);
    return __fdividef(x, 1.0f + e);
}

// ---------------------------------------------------------------------------
// Fused setup (257 blocks):
//   blocks 0..255 : grid-stride zero of g_node; blocks 0..31 ALSO do weight
//                   prep with coalesced 16B writes (8 k-halves per thread)
//   block  256    : dtype detect
// ---------------------------------------------------------------------------
__global__ void setup_kernel(const float* __restrict__ W1, const float* __restrict__ W2,
                             const float* __restrict__ W3, const float* __restrict__ W4,
                             const int* __restrict__ nbr, int n_words, int n4)
{
    int b = blockIdx.x;
    int tid = threadIdx.x;

    if (b < 256) {
        float4* gz = reinterpret_cast<float4*>(g_node);
        for (int i = b * 256 + tid; i < n4; i += 256 * 256)
            gz[i] = make_float4(0.f, 0.f, 0.f, 0.f);

        if (b < 32) {
            // 8192 threads, each emits 8 contiguous k-halves for one (l, n)
            int t = b * 256 + tid;            // 0..8191
            int l = t >> 11;
            int rem = t & 2047;
            int n = rem >> 4;                 // 0..127
            int k0 = (rem & 15) << 3;         // 0,8,...,120
            const float* W = (l == 0) ? W1 : (l == 1) ? W2 : (l == 2) ? W3 : W4;
            __half h[8];
#pragma unroll
            for (int i = 0; i < 8; i++)
                h[i] = __float2half_rn(W[(k0 + i) * 128 + n]);   // W[k][n]
            *reinterpret_cast<uint4*>(&g_wh[l * (128 * AP) + n * AP + k0]) =
                *reinterpret_cast<uint4*>(h);
        }
        return;
    }
    // dtype detection (block 256)
    __shared__ int any;
    if (tid == 0) any = 0;
    __syncthreads();
    int found = 0;
    for (int i = tid; i < 2048; i += blockDim.x) {
        int idx = 2 * i + 1;
        if (idx < n_words && nbr[idx] != 0) found = 1;
    }
    if (found) atomicOr(&any, 1);
    __syncthreads();
    if (tid == 0) g_is64 = (any == 0) ? 1 : 0;
}

// ---------------------------------------------------------------------------
// Edge pass: one warp = 4 edges, depth-2 prefetch on m_ji (MLP=2), PDL split.
// ---------------------------------------------------------------------------
__global__ void __launch_bounds__(256, 5) edge_kernel(
    const float* __restrict__ m_ji,
    const float* __restrict__ e_rbf,
    const int*   __restrict__ nbr,
    const float* __restrict__ W_edge,
    int E)
{
    __shared__ float sWe[6 * 128];
    int tid = threadIdx.x;
    for (int i = tid; i < 6 * 128; i += blockDim.x) sWe[i] = W_edge[i];
    __syncthreads();

    int warp = (int)((blockIdx.x * (long long)blockDim.x + tid) >> 5);
    int lane = tid & 31;
    long long e0 = (long long)warp * 4;
    if (e0 >= E) return;

    float rbf = 0.0f;
    if (lane < 24 && e0 * 6 + lane < (long long)E * 6)
        rbf = __ldcs(&e_rbf[e0 * 6 + lane]);

    const float4* we4 = reinterpret_cast<const float4*>(sWe);
    float4 wv[6];
#pragma unroll
    for (int r = 0; r < 6; r++) wv[r] = we4[r * 32 + lane];

    cudaGridDependencySynchronize();

    int is64 = g_is64;
    int d = 0;
    if (lane < 4 && e0 + lane < E)
        d = is64 ? __ldcs(&nbr[(e0 + lane) * 4 + 2]) : __ldcs(&nbr[(e0 + lane) * 2 + 1]);

    // depth-2 pipeline on m loads (per-warp MLP = 2)
    float4 mbuf[2];
    mbuf[0] = __ldcs(&reinterpret_cast<const float4*>(m_ji + e0 * EMB)[lane]);
    if (e0 + 1 < E)
        mbuf[1] = __ldcs(&reinterpret_cast<const float4*>(m_ji + (e0 + 1) * EMB)[lane]);

#pragma unroll
    for (int j = 0; j < 4; j++) {
        if (e0 + j >= E) break;
        float4 m = mbuf[j & 1];
        if (j + 2 < 4 && e0 + j + 2 < E)
            mbuf[j & 1] = __ldcs(&reinterpret_cast<const float4*>(m_ji + (e0 + j + 2) * EMB)[lane]);
        float4 w = make_float4(0.f, 0.f, 0.f, 0.f);
#pragma unroll
        for (int r = 0; r < 6; r++) {
            float c = __shfl_sync(0xffffffffu, rbf, j * 6 + r);
            w.x = fmaf(c, wv[r].x, w.x);
            w.y = fmaf(c, wv[r].y, w.y);
            w.z = fmaf(c, wv[r].z, w.z);
            w.w = fmaf(c, wv[r].w, w.w);
        }
        float4 o = make_float4(w.x * m.x, w.y * m.y, w.z * m.z, w.w * m.w);
        int dj = __shfl_sync(0xffffffffu, d, j);
        atomicAdd(reinterpret_cast<float4*>(&g_node[(long long)dj * EMB + lane * 4]), o);
    }
}

// ---------------------------------------------------------------------------
// MLP: pure fp16 mma.sync, 96 rows/CTA (6 m16 tiles), 2 CTAs/SM, 209 CTAs.
// smem: A(26112) B(34816) bias(1536) = 62464 B per CTA
// ---------------------------------------------------------------------------
#define SA    0
#define SB    26112
#define SBIAS 60928
#define SMEM_TOTAL (60928 + 1536)
#define B_CHUNKS 2176               // 34816 B / 16 = float4 count for one buffer

__device__ __forceinline__ void issue_b_copy(uint32_t sb, int layer, int tid) {
    const char* src = reinterpret_cast<const char*>(g_wh + layer * (128 * AP));
#pragma unroll 4
    for (int i = tid; i < B_CHUNKS; i += 256)
        cp_async16(sb + SB + i * 16, src + i * 16);
    cp_async_commit();
}

template <int MT>
__device__ __forceinline__ void layer_compute(
    uint32_t aA, uint32_t bB,
    const int* tiles, float acc[][8][4])
{
#pragma unroll
    for (int mt = 0; mt < MT; mt++)
#pragma unroll
        for (int nt = 0; nt < 8; nt++)
#pragma unroll
            for (int q = 0; q < 4; q++) acc[mt][nt][q] = 0.0f;

#pragma unroll
    for (int k0 = 0; k0 < 128; k0 += 16) {
        uint32_t ah[MT][4];
#pragma unroll
        for (int mt = 0; mt < MT; mt++) {
            uint32_t toff = (uint32_t)(tiles[mt] * 16 * (AP * 2)) + k0 * 2;
            ldsm_x4(aA + toff, ah[mt]);
        }
#pragma unroll
        for (int nt2 = 0; nt2 < 4; nt2++) {
            uint32_t bh[4];
            ldsm_x4(bB + nt2 * 16 * (AP * 2) + k0 * 2, bh);
#pragma unroll
            for (int nt = 0; nt < 2; nt++) {
                int nti = nt2 * 2 + nt;
#pragma unroll
                for (int mt = 0; mt < MT; mt++)
                    mma16816h(acc[mt][nti], ah[mt], bh[nt * 2], bh[nt * 2 + 1]);
            }
        }
    }
}

template <int MT>
__device__ __forceinline__ void layer_epilogue_act(
    char* smem, const float* bia, const int* tiles, float acc[][8][4],
    int wcol, int g, int t2)
{
#pragma unroll
    for (int mt = 0; mt < MT; mt++) {
        int rA = tiles[mt] * 16 + g;
        int rB = rA + 8;
#pragma unroll
        for (int nt = 0; nt < 8; nt++) {
            int col = wcol * 64 + nt * 8 + t2;
            float b0 = bia[col], b1v = bia[col + 1];
            float s0 = fast_swish(acc[mt][nt][0] + b0);
            float s1 = fast_swish(acc[mt][nt][1] + b1v);
            float s2 = fast_swish(acc[mt][nt][2] + b0);
            float s3 = fast_swish(acc[mt][nt][3] + b1v);
            *reinterpret_cast<uint32_t*>(smem + SA + rA * (AP * 2) + col * 2) =
                pack_h2(s0, s1);
            *reinterpret_cast<uint32_t*>(smem + SA + rB * (AP * 2) + col * 2) =
                pack_h2(s2, s3);
        }
    }
}

template <int MT>
__device__ __forceinline__ void layer_epilogue_out(
    float* __restrict__ out, const int* tiles, float acc[][8][4],
    int row0, int natoms, int wcol, int g, int t2)
{
#pragma unroll
    for (int mt = 0; mt < MT; mt++) {
        int rA = row0 + tiles[mt] * 16 + g;
        int rB = rA + 8;
#pragma unroll
        for (int nt = 0; nt < 8; nt++) {
            int col = wcol * 64 + nt * 8 + t2;
            if (rA < natoms)
                *reinterpret_cast<float2*>(&out[(long long)rA * EMB + col]) =
                    make_float2(acc[mt][nt][0], acc[mt][nt][1]);
            if (rB < natoms)
                *reinterpret_cast<float2*>(&out[(long long)rB * EMB + col]) =
                    make_float2(acc[mt][nt][2], acc[mt][nt][3]);
        }
    }
}

__global__ void __launch_bounds__(256, 2) mlp_kernel(
    const float* __restrict__ b1, const float* __restrict__ b2,
    const float* __restrict__ b3,
    float* __restrict__ out, int natoms)
{
    extern __shared__ char smem[];
    uint32_t sb = smem_to_u32(smem);
    int tid = threadIdx.x;
    int wid = tid >> 5;
    int lane = tid & 31;
    int wrow = wid >> 1;              // 0..3
    int wcol = wid & 1;               // 0..1
    int row0 = blockIdx.x * MROWS;

    int tiles[2];
    tiles[0] = wrow;
    tiles[1] = wrow + 4;              // valid only for wrow<2
    bool has2 = (wrow < 2);

    // pre-sync prologue: layer-0 weight copy + biases
    issue_b_copy(sb, 0, tid);

    if (tid < 128) {
        float* bia = reinterpret_cast<float*>(smem + SBIAS);
        bia[tid] = b1[tid];
        bia[128 + tid] = b2[tid];
        bia[256 + tid] = b3[tid];
    }

    // wait for edge kernel's atomics into g_node
    cudaGridDependencySynchronize();

    // First-layer A: fp32 g_node -> fp16, padded [row][k] layout.
    for (int i = tid; i < MROWS * 32; i += 256) {
        int r = i >> 5, c4 = i & 31;
        int gr = row0 + r;
        float4 v = make_float4(0.f, 0.f, 0.f, 0.f);
        if (gr < natoms)
            v = __ldcs(&reinterpret_cast<const float4*>(&g_node[(long long)gr * EMB])[c4]);
        uint2 hp;
        hp.x = pack_h2(v.x, v.y);
        hp.y = pack_h2(v.z, v.w);
        *reinterpret_cast<uint2*>(smem + SA + r * (AP * 2) + c4 * 8) = hp;
    }

    uint32_t a_lane = (uint32_t)((lane & 15) * (AP * 2) + ((lane >> 4) * 8) * 2);
    uint32_t aA = sb + SA + a_lane;
    uint32_t b_row = (uint32_t)(((lane >> 4) & 1) * 8 + (lane & 7));
    uint32_t b_k   = (uint32_t)(((lane >> 3) & 1) * 8);
    uint32_t b_off = (uint32_t)((wcol * 64 + b_row) * (AP * 2) + b_k * 2);
    uint32_t bB = sb + SB + b_off;

    const float* bias_all = reinterpret_cast<const float*>(smem + SBIAS);
    int g = lane >> 2;
    int t2 = (lane & 3) * 2;

    float acc[2][8][4];

    cp_async_wait0();
    __syncthreads();   // A + B(0) visible to all warps

    for (int layer = 0; layer < 4; layer++) {
        if (has2) layer_compute<2>(aA, bB, tiles, acc);
        else      layer_compute<1>(aA, bB, tiles, acc);

        __syncthreads();   // all A and B reads done -> safe to overwrite both

        if (layer < 3) {
            issue_b_copy(sb, layer + 1, tid);
            const float* bia = bias_all + layer * 128;
            if (has2) layer_epilogue_act<2>(smem, bia, tiles, acc, wcol, g, t2);
            else      layer_epilogue_act<1>(smem, bia, tiles, acc, wcol, g, t2);
            cp_async_wait0();
            __syncthreads();   // A(next) + B(next) visible
        } else {
            if (has2) layer_epilogue_out<2>(out, tiles, acc, row0, natoms, wcol, g, t2);
            else      layer_epilogue_out<1>(out, tiles, acc, row0, natoms, wcol, g, t2);
        }
    }
}

// ---------------------------------------------------------------------------
extern "C" void kernel_launch(void* const* d_in, const int* in_sizes, int n_in,
                              void* d_out, int out_size)
{
    const float* m_ji  = (const float*)d_in[0];
    const float* e_rbf = (const float*)d_in[1];
    const int*   nbr   = (const int*)d_in[2];

    int base = (n_in >= 12 && in_sizes[3] < 16) ? 4 : 3;
    const float* W_edge = (const float*)d_in[base + 0];
    const float* W1 = (const float*)d_in[base + 1];
    const float* b1 = (const float*)d_in[base + 2];
    const float* W2 = (const float*)d_in[base + 3];
    const float* b2 = (const float*)d_in[base + 4];
    const float* W3 = (const float*)d_in[base + 5];
    const float* b3 = (const float*)d_in[base + 6];
    const float* W4 = (const float*)d_in[base + 7];

    int E = in_sizes[1] / 6;
    int natoms = out_size / EMB;
    if (natoms > MAX_ATOMS) natoms = MAX_ATOMS;
    float* out = (float*)d_out;

    // setup: zero + coalesced weight prep + dtype detect
    int n4 = natoms * EMB / 4;
    setup_kernel<<<257, 256>>>(W1, W2, W3, W4, nbr, 2 * E, n4);

    cudaLaunchAttribute pdl[1];
    pdl[0].id = cudaLaunchAttributeProgrammaticStreamSerialization;
    pdl[0].val.programmaticStreamSerializationAllowed = 1;

    // edge pass (PDL-dependent on setup)
    {
        int warps = (E + 3) / 4;
        int eblocks = (warps + 7) / 8;
        cudaLaunchConfig_t cfg = {};
        cfg.gridDim = dim3((unsigned)eblocks, 1, 1);
        cfg.blockDim = dim3(256, 1, 1);
        cfg.dynamicSmemBytes = 0;
        cfg.stream = 0;
        cfg.attrs = pdl;
        cfg.numAttrs = 1;
        cudaLaunchKernelEx(&cfg, edge_kernel, m_ji, e_rbf, nbr, W_edge, E);
    }

    // MLP (PDL-dependent on edge): 209 CTAs, 2 CTAs/SM, single wave
    cudaFuncSetAttribute(mlp_kernel, cudaFuncAttributeMaxDynamicSharedMemorySize, SMEM_TOTAL);
    {
        int mlp_blocks = (natoms + MROWS - 1) / MROWS;
        cudaLaunchConfig_t cfg = {};
        cfg.gridDim = dim3((unsigned)mlp_blocks, 1, 1);
        cfg.blockDim = dim3(256, 1, 1);
        cfg.dynamicSmemBytes = SMEM_TOTAL;
        cfg.stream = 0;
        cfg.attrs = pdl;
        cfg.numAttrs = 1;
        cudaLaunchKernelEx(&cfg, mlp_kernel, b1, b2, b3, out, natoms);
    }
}